// round 1
// baseline (speedup 1.0000x reference)
#include <cuda_runtime.h>

// Problem constants (fixed by the dataset)
#define N_ROWS   2048
#define DIM      256
#define T_TRK    256
#define NCOLS_XY 16384   // T*Q
#define NCOLS_XX 2048

#define BM 128
#define BN 128
#define BK 16
#define TM 8
#define TN 8
#define NTHREADS 256
#define NCT_XY (NCOLS_XY / BN)   // 128
#define NCT_XX (NCOLS_XX / BN)   // 16

static __device__ float g_xy_tot[NCT_XY * N_ROWS];
static __device__ float g_xy_pos[NCT_XY * N_ROWS];
static __device__ float g_xx_tot[NCT_XX * N_ROWS];
static __device__ float g_xx_pos[NCT_XX * N_ROWS];
static __device__ float g_diag[N_ROWS];
static __device__ float g_num[N_ROWS];
static __device__ float g_den[N_ROWS];

// Fused GEMM + exp + (total, track-matched) row reduction.
// blockIdx.y < NCT_XY  : xy part (B = y flat [16384][256], col track = j & 255)
// blockIdx.y >= NCT_XY : xx part (B = x       [2048][256], col track = trk[j])
__global__ __launch_bounds__(NTHREADS)
void gemm_exp_reduce(const float* __restrict__ x,
                     const float* __restrict__ y,
                     const int*   __restrict__ trk)
{
    __shared__ float smem[2 * BK * BM];   // 16KB: As|Bs during mainloop, red buffers after
    float* As = smem;                     // [BK][BM] transposed
    float* Bs = smem + BK * BM;           // [BK][BN] transposed
    __shared__ int rowTid[BM];
    __shared__ int colTrk[BN];

    const int tid = threadIdx.x;
    const int bx  = blockIdx.x;
    const int by  = blockIdx.y;

    const bool isXX = (by >= NCT_XY);
    const int  ct   = isXX ? (by - NCT_XY) : by;
    const int  rowBase = bx * BM;
    const int  colBase = ct * BN;
    const float* B = isXX ? x : y;

    if (tid < BM) rowTid[tid] = trk[rowBase + tid];
    if (tid < BN) colTrk[tid] = isXX ? trk[colBase + tid]
                                     : ((colBase + tid) & (T_TRK - 1));

    const int tx = tid & 15;    // col lane: cols n*16 + tx
    const int ty = tid >> 4;    // row lane: rows m*16 + ty

    float acc[TM][TN];
    #pragma unroll
    for (int m = 0; m < TM; m++)
        #pragma unroll
        for (int n = 0; n < TN; n++) acc[m][n] = 0.f;

    for (int k0 = 0; k0 < DIM; k0 += BK) {
        __syncthreads();
        // Load BMxBK of A and BNxBK of B (512 float4 each, 2 per thread), store transposed
        #pragma unroll
        for (int i = 0; i < 2; i++) {
            int idx = tid + i * NTHREADS;      // 0..511
            int r   = idx >> 2;                // tile row
            int k4  = idx & 3;                 // float4 index along K
            float4 va = *reinterpret_cast<const float4*>(&x[(rowBase + r) * DIM + k0 + k4 * 4]);
            As[(k4 * 4 + 0) * BM + r] = va.x;
            As[(k4 * 4 + 1) * BM + r] = va.y;
            As[(k4 * 4 + 2) * BM + r] = va.z;
            As[(k4 * 4 + 3) * BM + r] = va.w;
            float4 vb = *reinterpret_cast<const float4*>(&B[(colBase + r) * DIM + k0 + k4 * 4]);
            Bs[(k4 * 4 + 0) * BN + r] = vb.x;
            Bs[(k4 * 4 + 1) * BN + r] = vb.y;
            Bs[(k4 * 4 + 2) * BN + r] = vb.z;
            Bs[(k4 * 4 + 3) * BN + r] = vb.w;
        }
        __syncthreads();
        #pragma unroll
        for (int kk = 0; kk < BK; kk++) {
            float ra[TM], rb[TN];
            #pragma unroll
            for (int m = 0; m < TM; m++) ra[m] = As[kk * BM + m * 16 + ty];
            #pragma unroll
            for (int n = 0; n < TN; n++) rb[n] = Bs[kk * BN + n * 16 + tx];
            #pragma unroll
            for (int m = 0; m < TM; m++)
                #pragma unroll
                for (int n = 0; n < TN; n++) acc[m][n] += ra[m] * rb[n];
        }
    }

    // Epilogue: exp + per-thread partial row sums
    const float INV_TEMP = 1.0f / 0.3f;
    const bool diagBlk = isXX && (bx == ct);   // block containing S_xx diagonal

    int myCtk[TN];
    #pragma unroll
    for (int n = 0; n < TN; n++) myCtk[n] = colTrk[n * 16 + tx];

    float tot[TM], pos[TM];
    #pragma unroll
    for (int m = 0; m < TM; m++) {
        const int rt = rowTid[m * 16 + ty];
        float t = 0.f, p = 0.f;
        #pragma unroll
        for (int n = 0; n < TN; n++) {
            float e = __expf(acc[m][n] * INV_TEMP);
            t += e;
            if (myCtk[n] == rt) p += e;
            if (diagBlk && (m == n) && (tx == ty))
                g_diag[rowBase + m * 16 + ty] = e;
        }
        tot[m] = t; pos[m] = p;
    }

    // Deterministic cross-thread row reduction (reuse smem)
    __syncthreads();
    float* redT = smem;             // [BM][16]
    float* redP = smem + BM * 16;   // [BM][16]
    #pragma unroll
    for (int m = 0; m < TM; m++) {
        int r = m * 16 + ty;
        redT[r * 16 + tx] = tot[m];
        redP[r * 16 + tx] = pos[m];
    }
    __syncthreads();

    if (tid < BM) {
        float st = 0.f, sp = 0.f;
        #pragma unroll
        for (int j = 0; j < 16; j++) { st += redT[tid * 16 + j]; sp += redP[tid * 16 + j]; }
        float* oT = isXX ? g_xx_tot : g_xy_tot;
        float* oP = isXX ? g_xx_pos : g_xy_pos;
        oT[ct * N_ROWS + rowBase + tid] = st;
        oP[ct * N_ROWS + rowBase + tid] = sp;
    }
}

// Per-row num/den from column-tile partials
__global__ void row_finalize()
{
    int i = blockIdx.x * blockDim.x + threadIdx.x;
    if (i >= N_ROWS) return;
    float xyT = 0.f, xyP = 0.f;
    #pragma unroll 4
    for (int c = 0; c < NCT_XY; c++) {
        xyT += g_xy_tot[c * N_ROWS + i];
        xyP += g_xy_pos[c * N_ROWS + i];
    }
    float xxT = 0.f, xxP = 0.f;
    #pragma unroll
    for (int c = 0; c < NCT_XX; c++) {
        xxT += g_xx_tot[c * N_ROWS + i];
        xxP += g_xx_pos[c * N_ROWS + i];
    }
    float dg = g_diag[i];
    g_num[i] = xyP + 0.5f * (xxP - dg);
    g_den[i] = (xyT - xyP) + (xxT - xxP);
}

// Per-track segment sums + loss + mean over present tracks. One block, deterministic.
__global__ void final_loss(const int* __restrict__ trk, float* __restrict__ out)
{
    int t = threadIdx.x;   // 256 threads = T tracks
    float num = 0.f, den = 0.f; int cnt = 0;
    for (int i = 0; i < N_ROWS; i++) {
        if (trk[i] == t) { num += g_num[i]; den += g_den[i]; cnt++; }
    }
    float loss = 0.f; int pres = 0;
    if (cnt > 0) { pres = 1; loss = -logf(num / (den + num)); }

    __shared__ float sL[T_TRK];
    __shared__ int   sP[T_TRK];
    sL[t] = loss; sP[t] = pres;
    __syncthreads();
    for (int s = T_TRK / 2; s > 0; s >>= 1) {
        if (t < s) { sL[t] += sL[t + s]; sP[t] += sP[t + s]; }
        __syncthreads();
    }
    if (t == 0) out[0] = sL[0] / (float)sP[0];
}

extern "C" void kernel_launch(void* const* d_in, const int* in_sizes, int n_in,
                              void* d_out, int out_size)
{
    const float* x   = (const float*)d_in[0];   // [2048, 256]
    const int*   trk = (const int*)  d_in[1];   // [2048]
    const float* y   = (const float*)d_in[2];   // [256, 64, 256] -> flat [16384, 256]
    float* out = (float*)d_out;

    dim3 grid(N_ROWS / BM, NCT_XY + NCT_XX);    // (16, 144)
    gemm_exp_reduce<<<grid, NTHREADS>>>(x, y, trk);
    row_finalize<<<N_ROWS / 256, 256>>>();
    final_loss<<<1, T_TRK>>>(trk, out);
}

// round 3
// speedup vs baseline: 4.4916x; 4.4916x over previous
#include <cuda_runtime.h>
#include <cuda_bf16.h>
#include <cstdint>

// ---------------- Problem constants ----------------
#define N_ROWS   2048
#define DIM      256
#define T_TRK    256
#define NCOLS_XY 16384            // T*Q
#define BM       128
#define BN       128
#define NCT_XY   (NCOLS_XY / BN)  // 128
#define NCT_XX   (N_ROWS   / BN)  // 16
#define NCT_TOT  (NCT_XY + NCT_XX) // 144
#define KCHUNK   32               // bf16 per K chunk (64B rows)
#define NCHUNK   (DIM / KCHUNK)   // 8

// ---------------- Device scratch ----------------
static __device__ __nv_bfloat16 g_xb[N_ROWS * DIM];
static __device__ __nv_bfloat16 g_yb[NCOLS_XY * DIM];
static __device__ float g_tot[NCT_TOT * N_ROWS];
static __device__ float g_pos[NCT_TOT * N_ROWS];
static __device__ float g_diag[N_ROWS];
static __device__ float g_num[N_ROWS];
static __device__ float g_den[N_ROWS];

// ---------------- PTX helpers (all baseline sm_80+, legal on plain sm_103) ----
__device__ __forceinline__ uint32_t smem_u32(const void* p) {
    uint32_t a;
    asm("{ .reg .u64 t; cvta.to.shared.u64 t, %1; cvt.u32.u64 %0, t; }" : "=r"(a) : "l"(p));
    return a;
}
__device__ __forceinline__ void cp_async16(uint32_t dst, const void* src) {
    asm volatile("cp.async.cg.shared.global [%0], [%1], 16;" :: "r"(dst), "l"(src));
}
#define CP_COMMIT() asm volatile("cp.async.commit_group;" ::: "memory")
#define CP_WAIT(n)  asm volatile("cp.async.wait_group %0;" :: "n"(n) : "memory")

__device__ __forceinline__ void ldsm4(uint32_t r[4], uint32_t addr) {
    asm volatile("ldmatrix.sync.aligned.m8n8.x4.shared.b16 {%0,%1,%2,%3}, [%4];"
                 : "=r"(r[0]), "=r"(r[1]), "=r"(r[2]), "=r"(r[3]) : "r"(addr));
}
__device__ __forceinline__ void mma16816(float c[4], const uint32_t a[4], const uint32_t b[2]) {
    asm volatile(
        "mma.sync.aligned.m16n8k16.row.col.f32.bf16.bf16.f32 "
        "{%0,%1,%2,%3}, {%4,%5,%6,%7}, {%8,%9}, {%0,%1,%2,%3};"
        : "+f"(c[0]), "+f"(c[1]), "+f"(c[2]), "+f"(c[3])
        : "r"(a[0]), "r"(a[1]), "r"(a[2]), "r"(a[3]), "r"(b[0]), "r"(b[1]));
}

// ---------------- fp32 -> bf16 conversion ----------------
__global__ void to_bf16(const float* __restrict__ s, __nv_bfloat16* __restrict__ d, int n4) {
    int i = blockIdx.x * blockDim.x + threadIdx.x;
    if (i < n4) {
        float4 v = reinterpret_cast<const float4*>(s)[i];
        __nv_bfloat162* o = reinterpret_cast<__nv_bfloat162*>(d);
        o[i * 2 + 0] = __floats2bfloat162_rn(v.x, v.y);
        o[i * 2 + 1] = __floats2bfloat162_rn(v.z, v.w);
    }
}

// ---------------- Fused HMMA GEMM + exp + row reductions ----------------
// grid (16, 144): blockIdx.y < 128 -> xy column tiles, >= 128 -> xx tiles.
__global__ __launch_bounds__(256)
void gemm_mma(const int* __restrict__ trk)
{
    // SW64-swizzled tiles: row = 64B (32 bf16), swizzle o ^ ((o>>3)&0x30)
    __shared__ __nv_bfloat16 As[2][BM * KCHUNK];   // 2 x 8KB
    __shared__ __nv_bfloat16 Bs[2][BN * KCHUNK];   // 2 x 8KB
    __shared__ int   colTrkS[BN];
    __shared__ int   rowTidS[BM];
    __shared__ float redT[BM * 2];
    __shared__ float redP[BM * 2];

    const int tid = threadIdx.x;
    const int wid = tid >> 5;
    const int lid = tid & 31;
    const int wm = wid & 3;      // warp m: rows wm*32..+31
    const int wn = wid >> 2;     // warp n: cols wn*64..+63

    const int bx = blockIdx.x;
    const int ct = blockIdx.y;
    const bool isXX = (ct >= NCT_XY);
    const int rowBase = bx * BM;
    const int colBase = isXX ? (ct - NCT_XY) * BN : ct * BN;
    const __nv_bfloat16* Bsrc = isXX ? g_xb : g_yb;
    const bool diagBlk = isXX && (colBase == rowBase);

    if (tid < BN) colTrkS[tid] = isXX ? trk[colBase + tid] : ((colBase + tid) & (T_TRK - 1));
    if (tid < BM) rowTidS[tid] = trk[rowBase + tid];

    const uint32_t sA = smem_u32(&As[0][0]);
    const uint32_t sB = smem_u32(&Bs[0][0]);

    // ---- precompute ldmatrix lane offsets (relative to stage base) ----
    // A: x4 -> lanes 0-7 rows0-7 klo | 8-15 rows8-15 klo | 16-23 rows0-7 khi | 24-31 rows8-15 khi
    uint32_t aOff[2][2];
    #pragma unroll
    for (int mt = 0; mt < 2; mt++) {
        int r = wm * 32 + mt * 16 + (lid & 7) + ((lid >> 3) & 1) * 8;
        #pragma unroll
        for (int s = 0; s < 2; s++) {
            uint32_t c = (uint32_t)(s * 32 + ((lid >> 4) & 1) * 16);
            aOff[mt][s] = (uint32_t)(r * 64) + (c ^ (uint32_t)((r & 6) << 3));
        }
    }
    // B: x4 -> lanes 0-7 n-tile0 klo | 8-15 ntile0 khi | 16-23 ntile1 klo | 24-31 ntile1 khi
    uint32_t bOff[4][2];
    #pragma unroll
    for (int ntp = 0; ntp < 4; ntp++) {
        int r = wn * 64 + ntp * 16 + (lid & 7) + ((lid >> 4) & 1) * 8;
        #pragma unroll
        for (int s = 0; s < 2; s++) {
            uint32_t c = (uint32_t)(s * 32 + ((lid >> 3) & 1) * 16);
            bOff[ntp][s] = (uint32_t)(r * 64) + (c ^ (uint32_t)((r & 6) << 3));
        }
    }

    float c[2][8][4];
    #pragma unroll
    for (int mt = 0; mt < 2; mt++)
        #pragma unroll
        for (int nt = 0; nt < 8; nt++)
            #pragma unroll
            for (int k = 0; k < 4; k++) c[mt][nt][k] = 0.f;

    // ---- async tile loader: 512 x 16B per tile, 2 per thread per tile ----
    auto load_chunk = [&](int stage, int kc) {
        const int kEl = kc * KCHUNK;
        uint32_t dstA = sA + (uint32_t)stage * (BM * KCHUNK * 2);
        uint32_t dstB = sB + (uint32_t)stage * (BN * KCHUNK * 2);
        #pragma unroll
        for (int i = 0; i < 2; i++) {
            int idx = tid + i * 256;            // 0..511
            int r = idx >> 2, c4 = idx & 3;
            uint32_t off = (uint32_t)(r * 64 + ((c4 * 16) ^ ((r & 6) << 3)));
            cp_async16(dstA + off, g_xb + (rowBase + r) * DIM + kEl + c4 * 8);
            cp_async16(dstB + off, Bsrc + (colBase + r) * DIM + kEl + c4 * 8);
        }
    };

    load_chunk(0, 0);
    CP_COMMIT();

    #pragma unroll
    for (int kc = 0; kc < NCHUNK; kc++) {
        if (kc < NCHUNK - 1) {
            load_chunk((kc + 1) & 1, kc + 1);
            CP_COMMIT();
            CP_WAIT(1);
        } else {
            CP_WAIT(0);
        }
        __syncthreads();

        const uint32_t baseA = sA + (uint32_t)(kc & 1) * (BM * KCHUNK * 2);
        const uint32_t baseB = sB + (uint32_t)(kc & 1) * (BN * KCHUNK * 2);
        #pragma unroll
        for (int s = 0; s < 2; s++) {
            uint32_t a[2][4], b[4][4];
            ldsm4(a[0], baseA + aOff[0][s]);
            ldsm4(a[1], baseA + aOff[1][s]);
            #pragma unroll
            for (int ntp = 0; ntp < 4; ntp++) ldsm4(b[ntp], baseB + bOff[ntp][s]);
            #pragma unroll
            for (int mt = 0; mt < 2; mt++)
                #pragma unroll
                for (int nt = 0; nt < 8; nt++)
                    mma16816(c[mt][nt], a[mt], &b[nt >> 1][(nt & 1) * 2]);
        }
        __syncthreads();   // protect stage kc&1 from the overwrite issued next iter
    }

    // ---- epilogue: exp + track-matched row partials, all in registers ----
    // C frag: c0,c1 -> row lid>>2, cols 2*(lid&3)+{0,1}; c2,c3 -> row +8
    const float INV_TEMP = 1.0f / 0.3f;
    float tot[2][2] = {{0.f, 0.f}, {0.f, 0.f}};
    float pos[2][2] = {{0.f, 0.f}, {0.f, 0.f}};
    int rt[2][2];
    #pragma unroll
    for (int mt = 0; mt < 2; mt++)
        #pragma unroll
        for (int h = 0; h < 2; h++)
            rt[mt][h] = rowTidS[wm * 32 + mt * 16 + (lid >> 2) + 8 * h];

    #pragma unroll
    for (int nt = 0; nt < 8; nt++) {
        const int colL = wn * 64 + nt * 8 + 2 * (lid & 3);
        const int ct0 = colTrkS[colL], ct1 = colTrkS[colL + 1];
        #pragma unroll
        for (int mt = 0; mt < 2; mt++)
            #pragma unroll
            for (int h = 0; h < 2; h++) {
                float e0 = __expf(c[mt][nt][2 * h + 0] * INV_TEMP);
                float e1 = __expf(c[mt][nt][2 * h + 1] * INV_TEMP);
                tot[mt][h] += e0 + e1;
                if (ct0 == rt[mt][h]) pos[mt][h] += e0;
                if (ct1 == rt[mt][h]) pos[mt][h] += e1;
                if (diagBlk) {
                    int rowg = rowBase + wm * 32 + mt * 16 + (lid >> 2) + 8 * h;
                    int colg = colBase + colL;
                    if (colg == rowg) g_diag[rowg] = e0;
                    if (colg + 1 == rowg) g_diag[rowg] = e1;
                }
            }
    }

    // quad-reduce across lanes holding the same rows (lanes differ only in lid&3)
    #pragma unroll
    for (int mt = 0; mt < 2; mt++)
        #pragma unroll
        for (int h = 0; h < 2; h++) {
            tot[mt][h] += __shfl_xor_sync(0xffffffffu, tot[mt][h], 1);
            tot[mt][h] += __shfl_xor_sync(0xffffffffu, tot[mt][h], 2);
            pos[mt][h] += __shfl_xor_sync(0xffffffffu, pos[mt][h], 1);
            pos[mt][h] += __shfl_xor_sync(0xffffffffu, pos[mt][h], 2);
        }

    if ((lid & 3) == 0) {
        #pragma unroll
        for (int mt = 0; mt < 2; mt++)
            #pragma unroll
            for (int h = 0; h < 2; h++) {
                int r = wm * 32 + mt * 16 + (lid >> 2) + 8 * h;
                redT[r * 2 + wn] = tot[mt][h];
                redP[r * 2 + wn] = pos[mt][h];
            }
    }
    __syncthreads();

    if (tid < BM) {
        g_tot[ct * N_ROWS + rowBase + tid] = redT[tid * 2] + redT[tid * 2 + 1];
        g_pos[ct * N_ROWS + rowBase + tid] = redP[tid * 2] + redP[tid * 2 + 1];
    }
}

// ---------------- Per-row num/den ----------------
__global__ void row_finalize()
{
    int i = blockIdx.x * blockDim.x + threadIdx.x;
    if (i >= N_ROWS) return;
    float xyT = 0.f, xyP = 0.f, xxT = 0.f, xxP = 0.f;
    #pragma unroll 4
    for (int c = 0; c < NCT_XY; c++) {
        xyT += g_tot[c * N_ROWS + i];
        xyP += g_pos[c * N_ROWS + i];
    }
    #pragma unroll
    for (int c = NCT_XY; c < NCT_TOT; c++) {
        xxT += g_tot[c * N_ROWS + i];
        xxP += g_pos[c * N_ROWS + i];
    }
    float dg = g_diag[i];
    g_num[i] = xyP + 0.5f * (xxP - dg);
    g_den[i] = (xyT - xyP) + (xxT - xxP);
}

// ---------------- Final per-track loss (deterministic, 1 block) ----------------
__global__ void final_loss(const int* __restrict__ trk, float* __restrict__ out)
{
    int t = threadIdx.x;
    float num = 0.f, den = 0.f; int cnt = 0;
    for (int i = 0; i < N_ROWS; i++) {
        if (trk[i] == t) { num += g_num[i]; den += g_den[i]; cnt++; }
    }
    float loss = 0.f; int pres = 0;
    if (cnt > 0) { pres = 1; loss = -logf(num / (den + num)); }

    __shared__ float sL[T_TRK];
    __shared__ int   sP[T_TRK];
    sL[t] = loss; sP[t] = pres;
    __syncthreads();
    for (int s = T_TRK / 2; s > 0; s >>= 1) {
        if (t < s) { sL[t] += sL[t + s]; sP[t] += sP[t + s]; }
        __syncthreads();
    }
    if (t == 0) out[0] = sL[0] / (float)sP[0];
}

extern "C" void kernel_launch(void* const* d_in, const int* in_sizes, int n_in,
                              void* d_out, int out_size)
{
    const float* x   = (const float*)d_in[0];   // [2048, 256]
    const int*   trk = (const int*)  d_in[1];   // [2048]
    const float* y   = (const float*)d_in[2];   // [256, 64, 256]
    float* out = (float*)d_out;

    __nv_bfloat16* xb_p; cudaGetSymbolAddress((void**)&xb_p, g_xb);
    __nv_bfloat16* yb_p; cudaGetSymbolAddress((void**)&yb_p, g_yb);

    to_bf16<<<(N_ROWS * DIM / 4 + 255) / 256, 256>>>(x, xb_p, N_ROWS * DIM / 4);
    to_bf16<<<(NCOLS_XY * DIM / 4 + 255) / 256, 256>>>(y, yb_p, NCOLS_XY * DIM / 4);

    dim3 grid(N_ROWS / BM, NCT_TOT);   // (16, 144)
    gemm_mma<<<grid, 256>>>(trk);
    row_finalize<<<N_ROWS / 256, 256>>>();
    final_loss<<<1, T_TRK>>>(trk, out);
}

// round 4
// speedup vs baseline: 8.2848x; 1.8445x over previous
#include <cuda_runtime.h>
#include <cuda_bf16.h>
#include <cstdint>

// ---------------- Problem constants ----------------
#define N_ROWS   2048
#define DIM      256
#define T_TRK    256
#define NCOLS_XY 16384            // T*Q
#define BM       128
#define BN       128
#define NCT_XY   (NCOLS_XY / BN)  // 128
#define NCT_XX   (N_ROWS   / BN)  // 16
#define NCT_TOT  (NCT_XY + NCT_XX) // 144
#define KCHUNK   32               // bf16 per K chunk (64B rows)
#define NCHUNK   (DIM / KCHUNK)   // 8

// ---------------- Device scratch ----------------
static __device__ __nv_bfloat16 g_xb[N_ROWS * DIM];
static __device__ __nv_bfloat16 g_yb[NCOLS_XY * DIM];
static __device__ float g_tot[NCT_TOT * N_ROWS];
static __device__ float g_pos[NCT_TOT * N_ROWS];
static __device__ float g_diag[N_ROWS];
static __device__ float g_num[N_ROWS];
static __device__ float g_den[N_ROWS];
static __device__ float g_pnum[T_TRK * 8];
static __device__ float g_pden[T_TRK * 8];
static __device__ int   g_pcnt[T_TRK * 8];

// ---------------- PTX helpers (baseline sm_80+, legal on plain sm_103) ----
__device__ __forceinline__ uint32_t smem_u32(const void* p) {
    uint32_t a;
    asm("{ .reg .u64 t; cvta.to.shared.u64 t, %1; cvt.u32.u64 %0, t; }" : "=r"(a) : "l"(p));
    return a;
}
__device__ __forceinline__ void cp_async16(uint32_t dst, const void* src) {
    asm volatile("cp.async.cg.shared.global [%0], [%1], 16;" :: "r"(dst), "l"(src));
}
#define CP_COMMIT() asm volatile("cp.async.commit_group;" ::: "memory")
#define CP_WAIT(n)  asm volatile("cp.async.wait_group %0;" :: "n"(n) : "memory")

__device__ __forceinline__ void ldsm4(uint32_t r[4], uint32_t addr) {
    asm volatile("ldmatrix.sync.aligned.m8n8.x4.shared.b16 {%0,%1,%2,%3}, [%4];"
                 : "=r"(r[0]), "=r"(r[1]), "=r"(r[2]), "=r"(r[3]) : "r"(addr));
}
__device__ __forceinline__ void mma16816(float c[4], const uint32_t a[4], const uint32_t b[2]) {
    asm volatile(
        "mma.sync.aligned.m16n8k16.row.col.f32.bf16.bf16.f32 "
        "{%0,%1,%2,%3}, {%4,%5,%6,%7}, {%8,%9}, {%0,%1,%2,%3};"
        : "+f"(c[0]), "+f"(c[1]), "+f"(c[2]), "+f"(c[3])
        : "r"(a[0]), "r"(a[1]), "r"(a[2]), "r"(a[3]), "r"(b[0]), "r"(b[1]));
}

// ---------------- fp32 -> bf16 conversion (x and y in one launch) -------------
#define NX4 (N_ROWS * DIM / 4)      // 131072
#define NY4 (NCOLS_XY * DIM / 4)    // 1048576
__global__ void to_bf16_all(const float* __restrict__ x, const float* __restrict__ y)
{
    int i = blockIdx.x * blockDim.x + threadIdx.x;
    const float* s; __nv_bfloat16* d; int j;
    if (i < NX4) { s = x; d = g_xb; j = i; }
    else if (i < NX4 + NY4) { s = y; d = g_yb; j = i - NX4; }
    else return;
    float4 v = reinterpret_cast<const float4*>(s)[j];
    __nv_bfloat162* o = reinterpret_cast<__nv_bfloat162*>(d);
    o[j * 2 + 0] = __floats2bfloat162_rn(v.x, v.y);
    o[j * 2 + 1] = __floats2bfloat162_rn(v.z, v.w);
}

// ---------------- Fused HMMA GEMM + exp + row reductions ----------------
// grid (16, 144): blockIdx.y < 128 -> xy column tiles, >= 128 -> xx tiles.
__global__ __launch_bounds__(256, 2)
void gemm_mma(const int* __restrict__ trk)
{
    // SW64-swizzled tiles: row = 64B (32 bf16), swizzle o ^ ((o>>3)&0x30)
    __shared__ __nv_bfloat16 As[2][BM * KCHUNK];   // 2 x 8KB
    __shared__ __nv_bfloat16 Bs[2][BN * KCHUNK];   // 2 x 8KB
    __shared__ int   colTrkS[BN];
    __shared__ int   rowTidS[BM];
    __shared__ float redT[BM * 2];
    __shared__ float redP[BM * 2];

    const int tid = threadIdx.x;
    const int wid = tid >> 5;
    const int lid = tid & 31;
    const int wm = wid & 3;      // warp m: rows wm*32..+31
    const int wn = wid >> 2;     // warp n: cols wn*64..+63

    const int bx = blockIdx.x;
    const int ct = blockIdx.y;
    const bool isXX = (ct >= NCT_XY);
    const int rowBase = bx * BM;
    const int colBase = isXX ? (ct - NCT_XY) * BN : ct * BN;
    const __nv_bfloat16* Bsrc = isXX ? g_xb : g_yb;
    const bool diagBlk = isXX && (colBase == rowBase);

    if (tid < BN) colTrkS[tid] = isXX ? trk[colBase + tid] : ((colBase + tid) & (T_TRK - 1));
    if (tid < BM) rowTidS[tid] = trk[rowBase + tid];

    const uint32_t sA = smem_u32(&As[0][0]);
    const uint32_t sB = smem_u32(&Bs[0][0]);

    // ---- ldmatrix lane offsets (relative to stage base) ----
    uint32_t aOff[2][2];
    #pragma unroll
    for (int mt = 0; mt < 2; mt++) {
        int r = wm * 32 + mt * 16 + (lid & 7) + ((lid >> 3) & 1) * 8;
        #pragma unroll
        for (int s = 0; s < 2; s++) {
            uint32_t c = (uint32_t)(s * 32 + ((lid >> 4) & 1) * 16);
            aOff[mt][s] = (uint32_t)(r * 64) + (c ^ (uint32_t)((r & 6) << 3));
        }
    }
    uint32_t bOff[4][2];
    #pragma unroll
    for (int ntp = 0; ntp < 4; ntp++) {
        int r = wn * 64 + ntp * 16 + (lid & 7) + ((lid >> 4) & 1) * 8;
        #pragma unroll
        for (int s = 0; s < 2; s++) {
            uint32_t c = (uint32_t)(s * 32 + ((lid >> 3) & 1) * 16);
            bOff[ntp][s] = (uint32_t)(r * 64) + (c ^ (uint32_t)((r & 6) << 3));
        }
    }

    float c[2][8][4];
    #pragma unroll
    for (int mt = 0; mt < 2; mt++)
        #pragma unroll
        for (int nt = 0; nt < 8; nt++)
            #pragma unroll
            for (int k = 0; k < 4; k++) c[mt][nt][k] = 0.f;

    auto load_chunk = [&](int stage, int kc) {
        const int kEl = kc * KCHUNK;
        uint32_t dstA = sA + (uint32_t)stage * (BM * KCHUNK * 2);
        uint32_t dstB = sB + (uint32_t)stage * (BN * KCHUNK * 2);
        #pragma unroll
        for (int i = 0; i < 2; i++) {
            int idx = tid + i * 256;            // 0..511
            int r = idx >> 2, c4 = idx & 3;
            uint32_t off = (uint32_t)(r * 64 + ((c4 * 16) ^ ((r & 6) << 3)));
            cp_async16(dstA + off, g_xb + (rowBase + r) * DIM + kEl + c4 * 8);
            cp_async16(dstB + off, Bsrc + (colBase + r) * DIM + kEl + c4 * 8);
        }
    };

    load_chunk(0, 0);
    CP_COMMIT();

    #pragma unroll
    for (int kc = 0; kc < NCHUNK; kc++) {
        if (kc < NCHUNK - 1) {
            load_chunk((kc + 1) & 1, kc + 1);
            CP_COMMIT();
            CP_WAIT(1);
        } else {
            CP_WAIT(0);
        }
        __syncthreads();

        const uint32_t baseA = sA + (uint32_t)(kc & 1) * (BM * KCHUNK * 2);
        const uint32_t baseB = sB + (uint32_t)(kc & 1) * (BN * KCHUNK * 2);
        #pragma unroll
        for (int s = 0; s < 2; s++) {
            uint32_t a[2][4], b[4][4];
            ldsm4(a[0], baseA + aOff[0][s]);
            ldsm4(a[1], baseA + aOff[1][s]);
            #pragma unroll
            for (int ntp = 0; ntp < 4; ntp++) ldsm4(b[ntp], baseB + bOff[ntp][s]);
            #pragma unroll
            for (int mt = 0; mt < 2; mt++)
                #pragma unroll
                for (int nt = 0; nt < 8; nt++)
                    mma16816(c[mt][nt], a[mt], &b[nt >> 1][(nt & 1) * 2]);
        }
        __syncthreads();   // protect stage kc&1 from next iteration's overwrite
    }

    // ---- epilogue: exp + track-matched row partials ----
    const float INV_TEMP = 1.0f / 0.3f;
    float tot[2][2] = {{0.f, 0.f}, {0.f, 0.f}};
    float pos[2][2] = {{0.f, 0.f}, {0.f, 0.f}};
    int rt[2][2];
    #pragma unroll
    for (int mt = 0; mt < 2; mt++)
        #pragma unroll
        for (int h = 0; h < 2; h++)
            rt[mt][h] = rowTidS[wm * 32 + mt * 16 + (lid >> 2) + 8 * h];

    #pragma unroll
    for (int nt = 0; nt < 8; nt++) {
        const int colL = wn * 64 + nt * 8 + 2 * (lid & 3);
        const int ct0 = colTrkS[colL], ct1 = colTrkS[colL + 1];
        #pragma unroll
        for (int mt = 0; mt < 2; mt++)
            #pragma unroll
            for (int h = 0; h < 2; h++) {
                float e0 = __expf(c[mt][nt][2 * h + 0] * INV_TEMP);
                float e1 = __expf(c[mt][nt][2 * h + 1] * INV_TEMP);
                tot[mt][h] += e0 + e1;
                if (ct0 == rt[mt][h]) pos[mt][h] += e0;
                if (ct1 == rt[mt][h]) pos[mt][h] += e1;
                if (diagBlk) {
                    int rowg = rowBase + wm * 32 + mt * 16 + (lid >> 2) + 8 * h;
                    int colg = colBase + colL;
                    if (colg == rowg) g_diag[rowg] = e0;
                    if (colg + 1 == rowg) g_diag[rowg] = e1;
                }
            }
    }

    #pragma unroll
    for (int mt = 0; mt < 2; mt++)
        #pragma unroll
        for (int h = 0; h < 2; h++) {
            tot[mt][h] += __shfl_xor_sync(0xffffffffu, tot[mt][h], 1);
            tot[mt][h] += __shfl_xor_sync(0xffffffffu, tot[mt][h], 2);
            pos[mt][h] += __shfl_xor_sync(0xffffffffu, pos[mt][h], 1);
            pos[mt][h] += __shfl_xor_sync(0xffffffffu, pos[mt][h], 2);
        }

    if ((lid & 3) == 0) {
        #pragma unroll
        for (int mt = 0; mt < 2; mt++)
            #pragma unroll
            for (int h = 0; h < 2; h++) {
                int r = wm * 32 + mt * 16 + (lid >> 2) + 8 * h;
                redT[r * 2 + wn] = tot[mt][h];
                redP[r * 2 + wn] = pos[mt][h];
            }
    }
    __syncthreads();

    if (tid < BM) {
        g_tot[ct * N_ROWS + rowBase + tid] = redT[tid * 2] + redT[tid * 2 + 1];
        g_pos[ct * N_ROWS + rowBase + tid] = redP[tid * 2] + redP[tid * 2 + 1];
    }
}

// ---------------- Per-row num/den: 32 blocks x (64 rows x 4 tile-groups) -------
__global__ __launch_bounds__(256)
void row_finalize()
{
    __shared__ float sXT[4][64], sXP[4][64], sQT[4][64], sQP[4][64];
    const int r = threadIdx.x & 63;          // row in block
    const int g = threadIdx.x >> 6;          // tile group 0..3 (36 tiles each)
    const int row = blockIdx.x * 64 + r;

    float xyT = 0.f, xyP = 0.f, xxT = 0.f, xxP = 0.f;
    #pragma unroll 4
    for (int c = g * 36; c < (g + 1) * 36; c++) {
        float t = g_tot[c * N_ROWS + row];
        float p = g_pos[c * N_ROWS + row];
        if (c < NCT_XY) { xyT += t; xyP += p; }
        else            { xxT += t; xxP += p; }
    }
    sXT[g][r] = xyT; sXP[g][r] = xyP; sQT[g][r] = xxT; sQP[g][r] = xxP;
    __syncthreads();

    if (g == 0) {
        float aT = sXT[0][r] + sXT[1][r] + sXT[2][r] + sXT[3][r];
        float aP = sXP[0][r] + sXP[1][r] + sXP[2][r] + sXP[3][r];
        float bT = sQT[0][r] + sQT[1][r] + sQT[2][r] + sQT[3][r];
        float bP = sQP[0][r] + sQP[1][r] + sQP[2][r] + sQP[3][r];
        float dg = g_diag[row];
        g_num[row] = aP + 0.5f * (bP - dg);
        g_den[row] = (aT - aP) + (bT - bP);
    }
}

// ---------------- Per-track partials: 8 blocks, each scans 256 rows -----------
__global__ __launch_bounds__(256)
void loss_partial(const int* __restrict__ trk)
{
    __shared__ float sN[256], sD[256];
    __shared__ int   sT[256];
    const int j = blockIdx.x;                 // row chunk
    const int t = threadIdx.x;                // track id
    const int base = j * 256;

    sN[t] = g_num[base + t];
    sD[t] = g_den[base + t];
    sT[t] = trk[base + t];
    __syncthreads();

    float num = 0.f, den = 0.f; int cnt = 0;
    #pragma unroll 8
    for (int i = 0; i < 256; i++) {
        if (sT[i] == t) { num += sN[i]; den += sD[i]; cnt++; }
    }
    g_pnum[t * 8 + j] = num;
    g_pden[t * 8 + j] = den;
    g_pcnt[t * 8 + j] = cnt;
}

// ---------------- Final reduce: 1 block, 256 threads --------------------------
__global__ __launch_bounds__(256)
void final_reduce(float* __restrict__ out)
{
    const int t = threadIdx.x;
    float num = 0.f, den = 0.f; int cnt = 0;
    #pragma unroll
    for (int j = 0; j < 8; j++) {
        num += g_pnum[t * 8 + j];
        den += g_pden[t * 8 + j];
        cnt += g_pcnt[t * 8 + j];
    }
    float loss = 0.f; int pres = 0;
    if (cnt > 0) { pres = 1; loss = -logf(num / (den + num)); }

    __shared__ float sL[T_TRK];
    __shared__ int   sP[T_TRK];
    sL[t] = loss; sP[t] = pres;
    __syncthreads();
    for (int s = T_TRK / 2; s > 0; s >>= 1) {
        if (t < s) { sL[t] += sL[t + s]; sP[t] += sP[t + s]; }
        __syncthreads();
    }
    if (t == 0) out[0] = sL[0] / (float)sP[0];
}

extern "C" void kernel_launch(void* const* d_in, const int* in_sizes, int n_in,
                              void* d_out, int out_size)
{
    const float* x   = (const float*)d_in[0];   // [2048, 256]
    const int*   trk = (const int*)  d_in[1];   // [2048]
    const float* y   = (const float*)d_in[2];   // [256, 64, 256]
    float* out = (float*)d_out;

    to_bf16_all<<<(NX4 + NY4 + 255) / 256, 256>>>(x, y);

    dim3 grid(N_ROWS / BM, NCT_TOT);   // (16, 144)
    gemm_mma<<<grid, 256>>>(trk);
    row_finalize<<<N_ROWS / 64, 256>>>();
    loss_partial<<<8, 256>>>(trk);
    final_reduce<<<1, 256>>>(out);
}